// round 2
// baseline (speedup 1.0000x reference)
#include <cuda_runtime.h>
#include <cstdint>

#define NCTA     125
#define NTHREADS 256         // 8 warps; warp w owns rows {2w, 2w+1} of its CTA's 16
#define RDIM     2000
#define CEXT     2048        // 2000 h + 28 x + 20 zero pad
#define XDIM     28
#define TSTEPS   28
#define BATCH    512
#define NSTEP    (BATCH*TSTEPS)
#define ODIM     10

// Static device scratch (no allocation anywhere)
__device__ float    g_h[2][CEXT];          // double-buffered hidden state
__device__ float    g_hlast[BATCH*RDIM];   // h at t = T-1 per batch element
__device__ unsigned g_flag[NCTA * 32];     // per-producer flag, 128B stride

// ---- packed f32x2 helpers ----
__device__ __forceinline__ unsigned long long fma2(unsigned long long a,
                                                   unsigned long long b,
                                                   unsigned long long c) {
    unsigned long long d;
    asm("fma.rn.f32x2 %0, %1, %2, %3;" : "=l"(d) : "l"(a), "l"(b), "l"(c));
    return d;
}
__device__ __forceinline__ unsigned long long pk2(float lo, float hi) {
    unsigned long long u;
    asm("mov.b64 %0, {%1, %2};" : "=l"(u)
        : "r"(__float_as_uint(lo)), "r"(__float_as_uint(hi)));
    return u;
}
__device__ __forceinline__ float lo32(unsigned long long v) { return __uint_as_float((unsigned)v); }
__device__ __forceinline__ float hi32(unsigned long long v) { return __uint_as_float((unsigned)(v >> 32)); }

// W_ext element: [W_res | W_in | 0-pad], row r, extended column c
__device__ __forceinline__ float wext(const float* __restrict__ Wres,
                                      const float* __restrict__ Win,
                                      int r, int c) {
    if (c < RDIM)        return Wres[r * RDIM + c];
    if (c < RDIM + XDIM) return Win[r * XDIM + (c - RDIM)];
    return 0.0f;
}

__global__ void reset_kernel() {
    const int t = blockIdx.x * blockDim.x + threadIdx.x;
    if (t < NCTA * 32) g_flag[t] = 0u;     // step-0 wait (>=0) passes immediately
    if (t < CEXT)      g_h[1][t] = 0.0f;   // h0 = 0 (buffer read by step 0)
}

__global__ void __launch_bounds__(NTHREADS, 1)
rnn_kernel(const float* __restrict__ x,
           const float* __restrict__ W_in,
           const float* __restrict__ W_res) {
    __shared__ __align__(16) float sh[CEXT];

    const int tid   = threadIdx.x;
    const int w     = tid >> 5;
    const int l     = tid & 31;
    const int rbase = blockIdx.x * 16;
    const int r0    = rbase + 2 * w;      // warp's two rows: r0, r0+1

    // ---- Gather W_ext slice into registers (column-pair packed, per row) ----
    // Lane l owns cols {4l..4l+3} + 128k for k=0..15 (matches conflict-free LDS).
    unsigned long long Wa[16][2], Wb[16][2];
#pragma unroll
    for (int k = 0; k < 16; ++k) {
#pragma unroll
        for (int j = 0; j < 2; ++j) {
            const int c = 4 * l + 128 * k + 2 * j;
            Wa[k][j] = pk2(wext(W_res, W_in, r0,     c),
                           wext(W_res, W_in, r0,     c + 1));
            Wb[k][j] = pk2(wext(W_res, W_in, r0 + 1, c),
                           wext(W_res, W_in, r0 + 1, c + 1));
        }
    }

    // Zero SMEM pad cols [2028, 2048) once; first in-loop __syncthreads orders it.
    if (tid < 5) ((float4*)sh)[507 + tid] = make_float4(0.f, 0.f, 0.f, 0.f);

    const unsigned long long z2 = pk2(0.f, 0.f);

    for (int s = 0; s < NSTEP; ++s) {
        // ---- Distributed wait + gather: thread i owns producer CTA i ----
        if (tid < NCTA) {
            unsigned v;
            const unsigned* fp = &g_flag[tid * 32];
            do {
                asm volatile("ld.acquire.gpu.u32 %0, [%1];"
                             : "=r"(v) : "l"(fp) : "memory");
            } while (v < (unsigned)s);
            const float4* src = (const float4*)g_h[(s + 1) & 1] + 4 * tid;
            float4* dst = (float4*)sh + 4 * tid;
            float4 c0 = __ldcg(src + 0), c1 = __ldcg(src + 1);
            float4 c2 = __ldcg(src + 2), c3 = __ldcg(src + 3);
            dst[0] = c0; dst[1] = c1; dst[2] = c2; dst[3] = c3;
        }
        if (tid >= 128 && tid < 135) {     // x_t: 28 floats = 7 float4 (no wait needed)
            const int j = tid - 128;
            ((float4*)sh)[500 + j] =
                __ldg((const float4*)(x + (size_t)s * XDIM) + j);
        }
        __syncthreads();

        // ---- Matvec: 2 rows x 64 cols per lane, packed f32x2 ----
        unsigned long long a0 = z2, a1 = z2, b0 = z2, b1 = z2;
#pragma unroll
        for (int k = 0; k < 16; ++k) {
            const ulonglong2 h2 = *(const ulonglong2*)(sh + 4 * l + 128 * k);
            a0 = fma2(Wa[k][0], h2.x, a0);
            a1 = fma2(Wa[k][1], h2.y, a1);
            b0 = fma2(Wb[k][0], h2.x, b0);
            b1 = fma2(Wb[k][1], h2.y, b1);
        }
        float s0 = (lo32(a0) + hi32(a0)) + (lo32(a1) + hi32(a1));
        float s1 = (lo32(b0) + hi32(b0)) + (lo32(b1) + hi32(b1));

        // ---- 5-stage warp butterfly (two independent chains) ----
#pragma unroll
        for (int m = 16; m >= 1; m >>= 1) {
            s0 += __shfl_xor_sync(0xffffffffu, s0, m);
            s1 += __shfl_xor_sync(0xffffffffu, s1, m);
        }

        // ---- tanh + publish (lane 0 of each warp stores its row pair) ----
        if (l == 0) {
            float2 hv;
            hv.x = tanhf(s0);
            hv.y = tanhf(s1);
            __stcg((float2*)&g_h[s & 1][r0], hv);
            if ((s % TSTEPS) == TSTEPS - 1)
                *(float2*)&g_hlast[(s / TSTEPS) * RDIM + r0] = hv;
        }
        __syncthreads();
        if (tid == 0) {
            const unsigned nv = (unsigned)s + 1u;
            asm volatile("st.release.gpu.u32 [%0], %1;"
                         :: "l"(&g_flag[blockIdx.x * 32]), "r"(nv) : "memory");
        }
    }
}

__global__ void out_kernel(const float* __restrict__ W_out,
                           float* __restrict__ out) {
    const int b   = blockIdx.x;
    const int tid = threadIdx.x;
    const float* __restrict__ h = g_hlast + b * RDIM;

    float acc[ODIM];
#pragma unroll
    for (int o = 0; o < ODIM; ++o) acc[o] = 0.f;

    for (int k = tid; k < RDIM; k += 256) {
        const float hv = h[k];
#pragma unroll
        for (int o = 0; o < ODIM; ++o)
            acc[o] = fmaf(W_out[o * RDIM + k], hv, acc[o]);
    }
#pragma unroll
    for (int o = 0; o < ODIM; ++o) {
#pragma unroll
        for (int m = 16; m >= 1; m >>= 1)
            acc[o] += __shfl_xor_sync(0xffffffffu, acc[o], m);
    }
    __shared__ float sp[8][ODIM];
    if ((tid & 31) == 0) {
#pragma unroll
        for (int o = 0; o < ODIM; ++o) sp[tid >> 5][o] = acc[o];
    }
    __syncthreads();
    if (tid < ODIM) {
        float s2 = 0.f;
#pragma unroll
        for (int ww = 0; ww < 8; ++ww) s2 += sp[ww][tid];
        out[b * ODIM + tid] = s2;
    }
}

extern "C" void kernel_launch(void* const* d_in, const int* in_sizes, int n_in,
                              void* d_out, int out_size) {
    (void)in_sizes; (void)n_in; (void)out_size;
    const float* x     = (const float*)d_in[0];
    const float* W_in  = (const float*)d_in[1];
    const float* W_res = (const float*)d_in[2];
    const float* W_out = (const float*)d_in[3];
    float* out = (float*)d_out;

    reset_kernel<<<16, 256>>>();                     // zero flags + h0 each replay
    rnn_kernel<<<NCTA, NTHREADS>>>(x, W_in, W_res);  // 125 CTAs, 1/SM, all resident
    out_kernel<<<BATCH, 256>>>(W_out, out);
}

// round 3
// speedup vs baseline: 1.2819x; 1.2819x over previous
#include <cuda_runtime.h>
#include <cstdint>

#define NCTA     125
#define NTHREADS 256         // 8 warps; warp w owns rows {2w, 2w+1}
#define RDIM     2000
#define CEXT     2048        // 2000 h + 28 x + 20 zero pad
#define XDIM     28
#define TSTEPS   28
#define BATCH    512
#define NSTEP    (BATCH*TSTEPS)
#define ODIM     10

// Static device scratch (no allocation anywhere)
__device__ float    g_h[2][CEXT];          // double-buffered [h | x_t | 0pad]
__device__ float    g_hlast[BATCH*RDIM];   // h at t = T-1 per batch element
__device__ unsigned g_ctr[8 * 64];         // 8 per-warp counters, 256B apart

// ---- packed f32x2 helpers ----
__device__ __forceinline__ unsigned long long fma2(unsigned long long a,
                                                   unsigned long long b,
                                                   unsigned long long c) {
    unsigned long long d;
    asm("fma.rn.f32x2 %0, %1, %2, %3;" : "=l"(d) : "l"(a), "l"(b), "l"(c));
    return d;
}
__device__ __forceinline__ unsigned long long pk2(float lo, float hi) {
    unsigned long long u;
    asm("mov.b64 %0, {%1, %2};" : "=l"(u)
        : "r"(__float_as_uint(lo)), "r"(__float_as_uint(hi)));
    return u;
}
__device__ __forceinline__ float lo32(unsigned long long v) { return __uint_as_float((unsigned)v); }
__device__ __forceinline__ float hi32(unsigned long long v) { return __uint_as_float((unsigned)(v >> 32)); }

// W_ext element: [W_res | W_in | 0-pad], row r, extended column c
__device__ __forceinline__ float wext(const float* __restrict__ Wres,
                                      const float* __restrict__ Win,
                                      int r, int c) {
    if (c < RDIM)        return Wres[r * RDIM + c];
    if (c < RDIM + XDIM) return Win[r * XDIM + (c - RDIM)];
    return 0.0f;
}

__global__ void reset_kernel(const float* __restrict__ x) {
    const int t = blockIdx.x * blockDim.x + threadIdx.x;
    if (t < 8 * 64) g_ctr[t] = 0u;
    if (t < RDIM)   g_h[1][t] = 0.0f;                    // h0 = 0
    if (t >= RDIM && t < RDIM + XDIM) g_h[1][t] = x[t - RDIM];  // x_0
    if (t >= RDIM + XDIM && t < CEXT) { g_h[1][t] = 0.0f; g_h[0][t] = 0.0f; }  // pads
}

__global__ void __launch_bounds__(NTHREADS, 1)
rnn_kernel(const float* __restrict__ x,
           const float* __restrict__ W_in,
           const float* __restrict__ W_res) {
    __shared__ __align__(16) float sh[CEXT];

    const int tid = threadIdx.x;
    const int w   = tid >> 5;
    const int l   = tid & 31;
    const int r0  = blockIdx.x * 16 + 2 * w;   // warp's two rows
    const bool xduty = (blockIdx.x == 0 && tid == 0);

    // ---- W_ext slice in registers: lane l owns cols {4l..4l+3} + 128k ----
    unsigned long long Wa[16][2], Wb[16][2];
#pragma unroll
    for (int k = 0; k < 16; ++k) {
#pragma unroll
        for (int j = 0; j < 2; ++j) {
            const int c = 4 * l + 128 * k + 2 * j;
            Wa[k][j] = pk2(wext(W_res, W_in, r0,     c),
                           wext(W_res, W_in, r0,     c + 1));
            Wb[k][j] = pk2(wext(W_res, W_in, r0 + 1, c),
                           wext(W_res, W_in, r0 + 1, c + 1));
        }
    }

    const unsigned long long z2 = pk2(0.f, 0.f);

    for (int s = 0; s < NSTEP; ++s) {
        // ---- prefetch x_{s+1} (CTA0 only; latency hidden behind poll/load) ----
        float4 xr[7];
        if (xduty && s + 1 < NSTEP) {
            const float4* xp = (const float4*)(x + (size_t)(s + 1) * XDIM);
#pragma unroll
            for (int j = 0; j < 7; ++j) xr[j] = __ldg(xp + j);
        }

        // ---- wait: lanes 0-7 of warp 0 poll the 8 per-warp counters ----
        if (tid < 8) {
            const unsigned target = (unsigned)s * NCTA;
            const unsigned* cp = &g_ctr[tid * 64];
            unsigned v;
            do {
                asm volatile("ld.acquire.gpu.u32 %0, [%1];"
                             : "=r"(v) : "l"(cp) : "memory");
            } while (v < target);
        }
        __syncthreads();   // A: release all warps; protects sh reuse

        // ---- stage h_ext (h | x | pad = 2048 floats) into SMEM, coalesced ----
        const float4* src = (const float4*)g_h[(s + 1) & 1];
        float4 v0 = __ldcg(src + tid);
        float4 v1 = __ldcg(src + tid + 256);
        ((float4*)sh)[tid]       = v0;
        ((float4*)sh)[tid + 256] = v1;
        __syncthreads();   // B: sh ready

        // ---- matvec: 2 rows x 64 cols per lane, packed f32x2 ----
        unsigned long long a0 = z2, a1 = z2, b0 = z2, b1 = z2;
#pragma unroll
        for (int k = 0; k < 16; ++k) {
            const ulonglong2 h2 = *(const ulonglong2*)(sh + 4 * l + 128 * k);
            a0 = fma2(Wa[k][0], h2.x, a0);
            a1 = fma2(Wa[k][1], h2.y, a1);
            b0 = fma2(Wb[k][0], h2.x, b0);
            b1 = fma2(Wb[k][1], h2.y, b1);
        }
        float s0 = (lo32(a0) + hi32(a0)) + (lo32(a1) + hi32(a1));
        float s1 = (lo32(b0) + hi32(b0)) + (lo32(b1) + hi32(b1));

        // ---- 5-stage butterfly (two independent chains) ----
#pragma unroll
        for (int m = 16; m >= 1; m >>= 1) {
            s0 += __shfl_xor_sync(0xffffffffu, s0, m);
            s1 += __shfl_xor_sync(0xffffffffu, s1, m);
        }

        // ---- x_{s+1} into next buffer (race-free: all step s-1 reads done) ----
        if (xduty && s + 1 < NSTEP) {
            float4* xd = (float4*)&g_h[s & 1][RDIM];
#pragma unroll
            for (int j = 0; j < 7; ++j) __stcg(xd + j, xr[j]);
        }

        // ---- tanh + publish + per-warp release-arrive (lane 0) ----
        if (l == 0) {
            float2 hv;
            hv.x = tanhf(s0);
            hv.y = tanhf(s1);
            __stcg((float2*)&g_h[s & 1][r0], hv);
            if ((s % TSTEPS) == TSTEPS - 1)
                *(float2*)&g_hlast[(s / TSTEPS) * RDIM + r0] = hv;
            asm volatile("red.release.gpu.global.add.u32 [%0], %1;"
                         :: "l"(&g_ctr[w * 64]), "r"(1u) : "memory");
        }
        // no tail sync: next iteration's bar A protects sh
    }
}

__global__ void out_kernel(const float* __restrict__ W_out,
                           float* __restrict__ out) {
    const int b   = blockIdx.x;
    const int tid = threadIdx.x;
    const float* __restrict__ h = g_hlast + b * RDIM;

    float acc[ODIM];
#pragma unroll
    for (int o = 0; o < ODIM; ++o) acc[o] = 0.f;

    for (int k = tid; k < RDIM; k += 256) {
        const float hv = h[k];
#pragma unroll
        for (int o = 0; o < ODIM; ++o)
            acc[o] = fmaf(W_out[o * RDIM + k], hv, acc[o]);
    }
#pragma unroll
    for (int o = 0; o < ODIM; ++o) {
#pragma unroll
        for (int m = 16; m >= 1; m >>= 1)
            acc[o] += __shfl_xor_sync(0xffffffffu, acc[o], m);
    }
    __shared__ float sp[8][ODIM];
    if ((tid & 31) == 0) {
#pragma unroll
        for (int o = 0; o < ODIM; ++o) sp[tid >> 5][o] = acc[o];
    }
    __syncthreads();
    if (tid < ODIM) {
        float s2 = 0.f;
#pragma unroll
        for (int ww = 0; ww < 8; ++ww) s2 += sp[ww][tid];
        out[b * ODIM + tid] = s2;
    }
}

extern "C" void kernel_launch(void* const* d_in, const int* in_sizes, int n_in,
                              void* d_out, int out_size) {
    (void)in_sizes; (void)n_in; (void)out_size;
    const float* x     = (const float*)d_in[0];
    const float* W_in  = (const float*)d_in[1];
    const float* W_res = (const float*)d_in[2];
    const float* W_out = (const float*)d_in[3];
    float* out = (float*)d_out;

    reset_kernel<<<16, 256>>>(x);                    // counters + h0 + x_0 + pads
    rnn_kernel<<<NCTA, NTHREADS>>>(x, W_in, W_res);  // 125 CTAs, 1/SM
    out_kernel<<<BATCH, 256>>>(W_out, out);
}